// round 14
// baseline (speedup 1.0000x reference)
#include <cuda_runtime.h>
#include <cstdint>

#define NQ        6
#define NPARAMS   15
#define NTHREADS  512
#define NWARPS    16
#define GRIDX     152
#define NROWS     16384
#define NCOLS     4096
#define STAGES    4
#define ROWBYTES  16384                 // 4096 floats
#define STAGEBYTES (2 * ROWBYTES)       // 2 rows per stage = 32KB
#define SMEM_RING  (STAGES * STAGEBYTES)// 128KB dynamic smem ring
#define NITER     54                    // ceil(108 rows / 2)

typedef unsigned long long u64;
typedef unsigned int u32;

__device__ __forceinline__ u64 pack2(float lo, float hi) {
    u64 r; asm("mov.b64 %0, {%1, %2};" : "=l"(r) : "f"(lo), "f"(hi)); return r;
}
__device__ __forceinline__ u64 bcast2(float v) {
    u64 r; asm("mov.b64 %0, {%1, %1};" : "=l"(r) : "f"(v)); return r;
}
__device__ __forceinline__ void fma2(u64& d, u64 a, u64 b) {
    asm("fma.rn.f32x2 %0, %1, %2, %0;" : "+l"(d) : "l"(a), "l"(b));
}
__device__ __forceinline__ void unpack2(u64 v, float& lo, float& hi) {
    asm("mov.b64 {%0, %1}, %2;" : "=f"(lo), "=f"(hi) : "l"(v));
}
__device__ __forceinline__ void cp16(u32 smem_dst, const void* gmem_src) {
    asm volatile("cp.async.cg.shared.global [%0], [%1], 16;"
                 :: "r"(smem_dst), "l"(gmem_src));
}
#define CP_COMMIT() asm volatile("cp.async.commit_group;")
#define CP_WAIT(n)  asm volatile("cp.async.wait_group %0;" :: "n"(n))

extern __shared__ char ring[];

__global__ __launch_bounds__(NTHREADS, 1)
void fused_hybrid_kernel(const float* __restrict__ x,
                         const float* __restrict__ W1,
                         const float* __restrict__ b1,
                         const float* __restrict__ qw,
                         const float* __restrict__ W2,
                         const float* __restrict__ b2,
                         float* __restrict__ out)
{
    __shared__ float sR[NQ][NQ];        // composed 6x6 Givens product
    __shared__ float sW2[NQ];
    __shared__ float sB1[NQ];
    __shared__ float sMisc[2];          // [0]=b2, [1]=sum(W2)
    __shared__ float sPart[2][NWARPS][12];

    const int tid  = threadIdx.x;
    const int lane = tid & 31;
    const int warp = tid >> 5;
    const int bid  = blockIdx.x;

    // ---- one-time per-block: fold the 15 RBS gates into a 6x6 matrix ----
    if (tid == 0) {
        const int qs[NPARAMS] = {4,3,2,4,1,3,0,2,4,1,3,2,4,3,4};
        float M[NQ][NQ];
        #pragma unroll
        for (int i = 0; i < NQ; i++)
            #pragma unroll
            for (int j = 0; j < NQ; j++)
                M[i][j] = (i == j) ? 1.0f : 0.0f;
        #pragma unroll
        for (int k = 0; k < NPARAMS; k++) {
            float s, c;
            sincosf(qw[k], &s, &c);
            const int q = qs[k];
            #pragma unroll
            for (int j = 0; j < NQ; j++) {
                float a0 = M[q][j], a1 = M[q + 1][j];
                M[q][j]     =  c * a0 + s * a1;
                M[q + 1][j] = -s * a0 + c * a1;
            }
        }
        float sw = 0.0f;
        #pragma unroll
        for (int j = 0; j < NQ; j++) {
            #pragma unroll
            for (int i = 0; i < NQ; i++) sR[j][i] = M[j][i];
            float w2v = W2[j];
            sW2[j] = w2v;
            sw += w2v;
            sB1[j] = b1[j];
        }
        sMisc[0] = b2[0];
        sMisc[1] = sw;
    }

    // ---- this thread's 8x6 slice of W1 in registers, packed f32x2 ----
    const float4* __restrict__ W14 = reinterpret_cast<const float4*>(W1);
    float w[48];
    #pragma unroll
    for (int f = 0; f < 6; f++) {                 // chunk A: cols 4t..4t+3
        float4 v = W14[6 * tid + f];
        w[4 * f + 0] = v.x; w[4 * f + 1] = v.y;
        w[4 * f + 2] = v.z; w[4 * f + 3] = v.w;
    }
    #pragma unroll
    for (int f = 0; f < 6; f++) {                 // chunk B: cols 2048+4t..
        float4 v = W14[3072 + 6 * tid + f];
        w[24 + 4 * f + 0] = v.x; w[24 + 4 * f + 1] = v.y;
        w[24 + 4 * f + 2] = v.z; w[24 + 4 * f + 3] = v.w;
    }
    u64 wp[8][3];
    #pragma unroll
    for (int dl = 0; dl < 8; dl++)
        #pragma unroll
        for (int p = 0; p < 3; p++)
            wp[dl][p] = pack2(w[dl * 6 + 2 * p], w[dl * 6 + 2 * p + 1]);

    // ---- cp.async ring: fill a stage with row-pair j (rows 2j, 2j+1 of this block) ----
    const u32 ring_s = (u32)__cvta_generic_to_shared(ring);
    const u32 slotA  = ring_s + (u32)tid * 16u;

    auto fill_stage = [&](int stage, int j) {
        long r0 = bid + (long)(2 * j) * GRIDX;
        long r1 = r0 + GRIDX;
        if (r0 > NROWS - 1) r0 = NROWS - 1;
        if (r1 > NROWS - 1) r1 = NROWS - 1;
        const float* s0 = x + r0 * NCOLS + tid * 4;
        const float* s1 = x + r1 * NCOLS + tid * 4;
        u32 d = slotA + (u32)stage * STAGEBYTES;
        cp16(d,             s0);
        cp16(d + 8192u,     s0 + 2048);
        cp16(d + 16384u,    s1);
        cp16(d + 24576u,    s1 + 2048);
        CP_COMMIT();
    };

    #pragma unroll
    for (int s = 0; s < STAGES; s++) fill_stage(s, s);

    __syncthreads();   // sR/sW2/... ready (ring slots are self-owned; no barrier needed)

    for (int it = 0; it < NITER; ++it) {
        const int stage = it & (STAGES - 1);
        const int par   = it & 1;

        CP_WAIT(STAGES - 1);   // oldest stage landed (self-owned slots)

        const float4* st = reinterpret_cast<const float4*>(ring + stage * STAGEBYTES);
        float4 a0  = st[tid];          // row0, cols 4t..4t+3
        float4 b0  = st[512 + tid];    // row0, cols 2048+4t..
        float4 a1  = st[1024 + tid];   // row1, cols 4t..4t+3
        float4 b1v = st[1536 + tid];   // row1, cols 2048+4t..

        u64 acc0[3] = {0ull, 0ull, 0ull};
        u64 acc1[3] = {0ull, 0ull, 0ull};
        {
            float xs0[8] = {a0.x, a0.y, a0.z, a0.w, b0.x, b0.y, b0.z, b0.w};
            float xs1[8] = {a1.x, a1.y, a1.z, a1.w, b1v.x, b1v.y, b1v.z, b1v.w};
            #pragma unroll
            for (int dl = 0; dl < 8; dl++) {
                u64 v0 = bcast2(xs0[dl]);
                u64 v1 = bcast2(xs1[dl]);
                fma2(acc0[0], v0, wp[dl][0]);
                fma2(acc1[0], v1, wp[dl][0]);
                fma2(acc0[1], v0, wp[dl][1]);
                fma2(acc1[1], v1, wp[dl][1]);
                fma2(acc0[2], v0, wp[dl][2]);
                fma2(acc1[2], v1, wp[dl][2]);
            }
        }

        // ---- warp reduce 12 partial sums (2 rows x 6) ----
        float s[12];
        unpack2(acc0[0], s[0],  s[1]);
        unpack2(acc0[1], s[2],  s[3]);
        unpack2(acc0[2], s[4],  s[5]);
        unpack2(acc1[0], s[6],  s[7]);
        unpack2(acc1[1], s[8],  s[9]);
        unpack2(acc1[2], s[10], s[11]);
        #pragma unroll
        for (int o = 16; o > 0; o >>= 1) {
            #pragma unroll
            for (int j = 0; j < 12; j++)
                s[j] += __shfl_down_sync(0xffffffffu, s[j], o);
        }
        if (lane == 0) {
            #pragma unroll
            for (int j = 0; j < 12; j++)
                sPart[par][warp][j] = s[j];
        }
        __syncthreads();

        // ---- finalize: two rotating warps, one per row ----
        const int fin0 = (it & 7) << 6;
        if (tid == fin0 || tid == fin0 + 32) {
            const int half = (tid == fin0) ? 0 : 6;
            long row = bid + (long)(2 * it + (half ? 1 : 0)) * GRIDX;
            if (row < NROWS) {
                float h[NQ];
                #pragma unroll
                for (int j = 0; j < NQ; j++) h[j] = sB1[j];
                #pragma unroll
                for (int wdx = 0; wdx < NWARPS; wdx++)
                    #pragma unroll
                    for (int j = 0; j < NQ; j++)
                        h[j] += sPart[par][wdx][half + j];

                float ss = 0.0f;
                #pragma unroll
                for (int j = 0; j < NQ; j++) ss += h[j] * h[j];

                float dw = 0.0f;
                #pragma unroll
                for (int j = 0; j < NQ; j++) {
                    float g = 0.0f;
                    #pragma unroll
                    for (int i = 0; i < NQ; i++) g = fmaf(sR[j][i], h[i], g);
                    dw = fmaf(sW2[j], g * g, dw);
                }
                float t = (ss > 0.0f) ? (sMisc[0] + sMisc[1] - 2.0f * dw / ss)
                                      : sMisc[0];
                out[row] = 1.0f / (1.0f + __expf(-t));
            }
        }

        // ---- refill the stage we just consumed (self-owned slots) ----
        fill_stage(stage, it + STAGES);
    }
}

extern "C" void kernel_launch(void* const* d_in, const int* in_sizes, int n_in,
                              void* d_out, int out_size) {
    const float* x  = (const float*)d_in[0];
    const float* W1 = (const float*)d_in[1];
    const float* b1 = (const float*)d_in[2];
    const float* qw = (const float*)d_in[3];
    const float* W2 = (const float*)d_in[4];
    const float* b2 = (const float*)d_in[5];
    float* out = (float*)d_out;

    cudaFuncSetAttribute(fused_hybrid_kernel,
                         cudaFuncAttributeMaxDynamicSharedMemorySize, SMEM_RING);
    fused_hybrid_kernel<<<GRIDX, NTHREADS, SMEM_RING>>>(x, W1, b1, qw, W2, b2, out);
}

// round 15
// speedup vs baseline: 1.0004x; 1.0004x over previous
#include <cuda_runtime.h>
#include <cstdint>

#define NQ        6
#define NPARAMS   15
#define NTHREADS  512
#define NWARPS    16
#define GRIDX     152
#define NROWS     16384
#define NCOLS     4096
#define STAGES    4
#define ROWBYTES  16384                 // 4096 floats
#define STAGEBYTES (2 * ROWBYTES)       // 2 rows per stage = 32KB
#define SMEM_RING  (STAGES * STAGEBYTES)// 128KB dynamic smem ring
#define NITER     54                    // ceil(108 rows / 2)

typedef unsigned long long u64;
typedef unsigned int u32;

__device__ __forceinline__ u64 pack2(float lo, float hi) {
    u64 r; asm("mov.b64 %0, {%1, %2};" : "=l"(r) : "f"(lo), "f"(hi)); return r;
}
__device__ __forceinline__ u64 bcast2(float v) {
    u64 r; asm("mov.b64 %0, {%1, %1};" : "=l"(r) : "f"(v)); return r;
}
__device__ __forceinline__ void fma2(u64& d, u64 a, u64 b) {
    asm("fma.rn.f32x2 %0, %1, %2, %0;" : "+l"(d) : "l"(a), "l"(b));
}
__device__ __forceinline__ void unpack2(u64 v, float& lo, float& hi) {
    asm("mov.b64 {%0, %1}, %2;" : "=f"(lo), "=f"(hi) : "l"(v));
}
__device__ __forceinline__ void cp16(u32 smem_dst, const void* gmem_src) {
    asm volatile("cp.async.cg.shared.global [%0], [%1], 16;"
                 :: "r"(smem_dst), "l"(gmem_src));
}
#define CP_COMMIT() asm volatile("cp.async.commit_group;")
#define CP_WAIT(n)  asm volatile("cp.async.wait_group %0;" :: "n"(n))

extern __shared__ char ring[];

__global__ __launch_bounds__(NTHREADS, 1)
void fused_hybrid_kernel(const float* __restrict__ x,
                         const float* __restrict__ W1,
                         const float* __restrict__ b1,
                         const float* __restrict__ qw,
                         const float* __restrict__ W2,
                         const float* __restrict__ b2,
                         float* __restrict__ out)
{
    __shared__ float sR[NQ][NQ];        // composed 6x6 Givens product
    __shared__ float sW2[NQ];
    __shared__ float sB1[NQ];
    __shared__ float sMisc[2];          // [0]=b2, [1]=sum(W2)
    __shared__ float sPart[2][NWARPS][12];

    const int tid  = threadIdx.x;
    const int lane = tid & 31;
    const int warp = tid >> 5;
    const int bid  = blockIdx.x;

    // ---- one-time per-block: fold the 15 RBS gates into a 6x6 matrix ----
    if (tid == 0) {
        const int qs[NPARAMS] = {4,3,2,4,1,3,0,2,4,1,3,2,4,3,4};
        float M[NQ][NQ];
        #pragma unroll
        for (int i = 0; i < NQ; i++)
            #pragma unroll
            for (int j = 0; j < NQ; j++)
                M[i][j] = (i == j) ? 1.0f : 0.0f;
        #pragma unroll
        for (int k = 0; k < NPARAMS; k++) {
            float s, c;
            sincosf(qw[k], &s, &c);
            const int q = qs[k];
            #pragma unroll
            for (int j = 0; j < NQ; j++) {
                float a0 = M[q][j], a1 = M[q + 1][j];
                M[q][j]     =  c * a0 + s * a1;
                M[q + 1][j] = -s * a0 + c * a1;
            }
        }
        float sw = 0.0f;
        #pragma unroll
        for (int j = 0; j < NQ; j++) {
            #pragma unroll
            for (int i = 0; i < NQ; i++) sR[j][i] = M[j][i];
            float w2v = W2[j];
            sW2[j] = w2v;
            sw += w2v;
            sB1[j] = b1[j];
        }
        sMisc[0] = b2[0];
        sMisc[1] = sw;
    }

    // ---- this thread's 8x6 slice of W1 in registers, packed f32x2 ----
    const float4* __restrict__ W14 = reinterpret_cast<const float4*>(W1);
    float w[48];
    #pragma unroll
    for (int f = 0; f < 6; f++) {                 // chunk A: cols 4t..4t+3
        float4 v = W14[6 * tid + f];
        w[4 * f + 0] = v.x; w[4 * f + 1] = v.y;
        w[4 * f + 2] = v.z; w[4 * f + 3] = v.w;
    }
    #pragma unroll
    for (int f = 0; f < 6; f++) {                 // chunk B: cols 2048+4t..
        float4 v = W14[3072 + 6 * tid + f];
        w[24 + 4 * f + 0] = v.x; w[24 + 4 * f + 1] = v.y;
        w[24 + 4 * f + 2] = v.z; w[24 + 4 * f + 3] = v.w;
    }
    u64 wp[8][3];
    #pragma unroll
    for (int dl = 0; dl < 8; dl++)
        #pragma unroll
        for (int p = 0; p < 3; p++)
            wp[dl][p] = pack2(w[dl * 6 + 2 * p], w[dl * 6 + 2 * p + 1]);

    // ---- cp.async ring: fill a stage with row-pair j (rows 2j, 2j+1 of this block) ----
    const u32 ring_s = (u32)__cvta_generic_to_shared(ring);
    const u32 slotA  = ring_s + (u32)tid * 16u;

    auto fill_stage = [&](int stage, int j) {
        long r0 = bid + (long)(2 * j) * GRIDX;
        long r1 = r0 + GRIDX;
        if (r0 > NROWS - 1) r0 = NROWS - 1;
        if (r1 > NROWS - 1) r1 = NROWS - 1;
        const float* s0 = x + r0 * NCOLS + tid * 4;
        const float* s1 = x + r1 * NCOLS + tid * 4;
        u32 d = slotA + (u32)stage * STAGEBYTES;
        cp16(d,             s0);
        cp16(d + 8192u,     s0 + 2048);
        cp16(d + 16384u,    s1);
        cp16(d + 24576u,    s1 + 2048);
        CP_COMMIT();
    };

    #pragma unroll
    for (int s = 0; s < STAGES; s++) fill_stage(s, s);

    __syncthreads();   // sR/sW2/... ready (ring slots are self-owned; no barrier needed)

    for (int it = 0; it < NITER; ++it) {
        const int stage = it & (STAGES - 1);
        const int par   = it & 1;

        CP_WAIT(STAGES - 1);   // oldest stage landed (self-owned slots)

        const float4* st = reinterpret_cast<const float4*>(ring + stage * STAGEBYTES);
        float4 a0  = st[tid];          // row0, cols 4t..4t+3
        float4 b0  = st[512 + tid];    // row0, cols 2048+4t..
        float4 a1  = st[1024 + tid];   // row1, cols 4t..4t+3
        float4 b1v = st[1536 + tid];   // row1, cols 2048+4t..

        u64 acc0[3] = {0ull, 0ull, 0ull};
        u64 acc1[3] = {0ull, 0ull, 0ull};
        {
            float xs0[8] = {a0.x, a0.y, a0.z, a0.w, b0.x, b0.y, b0.z, b0.w};
            float xs1[8] = {a1.x, a1.y, a1.z, a1.w, b1v.x, b1v.y, b1v.z, b1v.w};
            #pragma unroll
            for (int dl = 0; dl < 8; dl++) {
                u64 v0 = bcast2(xs0[dl]);
                u64 v1 = bcast2(xs1[dl]);
                fma2(acc0[0], v0, wp[dl][0]);
                fma2(acc1[0], v1, wp[dl][0]);
                fma2(acc0[1], v0, wp[dl][1]);
                fma2(acc1[1], v1, wp[dl][1]);
                fma2(acc0[2], v0, wp[dl][2]);
                fma2(acc1[2], v1, wp[dl][2]);
            }
        }

        // ---- warp reduce 12 partial sums (2 rows x 6) ----
        float s[12];
        unpack2(acc0[0], s[0],  s[1]);
        unpack2(acc0[1], s[2],  s[3]);
        unpack2(acc0[2], s[4],  s[5]);
        unpack2(acc1[0], s[6],  s[7]);
        unpack2(acc1[1], s[8],  s[9]);
        unpack2(acc1[2], s[10], s[11]);
        #pragma unroll
        for (int o = 16; o > 0; o >>= 1) {
            #pragma unroll
            for (int j = 0; j < 12; j++)
                s[j] += __shfl_down_sync(0xffffffffu, s[j], o);
        }
        if (lane == 0) {
            #pragma unroll
            for (int j = 0; j < 12; j++)
                sPart[par][warp][j] = s[j];
        }
        __syncthreads();

        // ---- finalize: two rotating warps, one per row ----
        const int fin0 = (it & 7) << 6;
        if (tid == fin0 || tid == fin0 + 32) {
            const int half = (tid == fin0) ? 0 : 6;
            long row = bid + (long)(2 * it + (half ? 1 : 0)) * GRIDX;
            if (row < NROWS) {
                float h[NQ];
                #pragma unroll
                for (int j = 0; j < NQ; j++) h[j] = sB1[j];
                #pragma unroll
                for (int wdx = 0; wdx < NWARPS; wdx++)
                    #pragma unroll
                    for (int j = 0; j < NQ; j++)
                        h[j] += sPart[par][wdx][half + j];

                float ss = 0.0f;
                #pragma unroll
                for (int j = 0; j < NQ; j++) ss += h[j] * h[j];

                float dw = 0.0f;
                #pragma unroll
                for (int j = 0; j < NQ; j++) {
                    float g = 0.0f;
                    #pragma unroll
                    for (int i = 0; i < NQ; i++) g = fmaf(sR[j][i], h[i], g);
                    dw = fmaf(sW2[j], g * g, dw);
                }
                float t = (ss > 0.0f) ? (sMisc[0] + sMisc[1] - 2.0f * dw / ss)
                                      : sMisc[0];
                out[row] = 1.0f / (1.0f + __expf(-t));
            }
        }

        // ---- refill the stage we just consumed (self-owned slots) ----
        fill_stage(stage, it + STAGES);
    }
}

extern "C" void kernel_launch(void* const* d_in, const int* in_sizes, int n_in,
                              void* d_out, int out_size) {
    const float* x  = (const float*)d_in[0];
    const float* W1 = (const float*)d_in[1];
    const float* b1 = (const float*)d_in[2];
    const float* qw = (const float*)d_in[3];
    const float* W2 = (const float*)d_in[4];
    const float* b2 = (const float*)d_in[5];
    float* out = (float*)d_out;

    cudaFuncSetAttribute(fused_hybrid_kernel,
                         cudaFuncAttributeMaxDynamicSharedMemorySize, SMEM_RING);
    fused_hybrid_kernel<<<GRIDX, NTHREADS, SMEM_RING>>>(x, W1, b1, qw, W2, b2, out);
}